// round 6
// baseline (speedup 1.0000x reference)
#include <cuda_runtime.h>
#include <math.h>
#include <stdint.h>

#define BATCH 2048
#define DIN   512
#define DOUT  512
#define DINT  512
#define DNL   256

// ---------------- device scratch ----------------
__device__ __align__(16) float g_WLU[512 * 1024];
__device__ __align__(16) float g_Dinv[64 * 64];
__device__ __align__(16) float g_RP[64 * 1024];
__device__ __align__(16) float g_a[BATCH * DNL];
__device__ __align__(16) float g_wm[BATCH * DNL];
__device__ __align__(16) float g_rhs[BATCH * DINT];
__device__ __align__(16) float g_xn[BATCH * DINT];
__device__ __align__(16) float g_D11T[DNL * DNL];
__device__ __align__(16) float g_c1x0[DNL];
__device__ __align__(16) float g_fx0[DINT];

// ---------------- small mat-vec ----------------
__global__ void mv_kernel(const float* __restrict__ Mtx, const float* __restrict__ x,
                          int N, int K, int which) {
    float* out = which ? g_fx0 : g_c1x0;
    int n = blockIdx.x * blockDim.x + threadIdx.x;
    if (n >= N) return;
    const float4* r  = (const float4*)(Mtx + (size_t)n * K);
    const float4* xv = (const float4*)x;
    float s = 0.f;
    for (int k = 0; k < K / 4; ++k) {
        float4 a = r[k], b = xv[k];
        s += a.x * b.x + a.y * b.y + a.z * b.z + a.w * b.w;
    }
    out[n] = s;
}

// ---------------- D11 transpose ----------------
__global__ void d11t_kernel(const float* __restrict__ D) {
    __shared__ float t[32][33];
    int bx = blockIdx.x * 32, by = blockIdx.y * 32;
    int tx = threadIdx.x, ty = threadIdx.y;  // (32,8)
    for (int i = 0; i < 32; i += 8)
        t[ty + i][tx] = D[(size_t)(by + ty + i) * 256 + bx + tx];
    __syncthreads();
    for (int i = 0; i < 32; i += 8)
        g_D11T[(size_t)(bx + ty + i) * 256 + by + tx] = t[tx][ty + i];
}

// ---------------- Gauss-Jordan: init W = [E | I] ----------------
__global__ void gj_init_kernel(const float* __restrict__ E) {
    int row = blockIdx.x;
    for (int c = threadIdx.x; c < 1024; c += blockDim.x) {
        g_WLU[(size_t)row * 1024 + c] =
            (c < 512) ? E[(size_t)row * 512 + c] : ((c - 512) == row ? 1.f : 0.f);
    }
}

// ---------------- fast 64x64 pivot-block inverse: register resident ----------------
// 256 threads; thread (rg = t>>4, cg = t&15) owns rows [rg*4,rg*4+4) x cols [cg*8,cg*8+8)
// of the 64x128 augmented [P | I] block. Per iteration: publish row j + col j, rank-1.
__global__ void __launch_bounds__(256) gj_pivot_fast(int kb) {
    __shared__ float rowbuf[128];
    __shared__ float colbuf[64];
    const int pc = kb * 64;
    const int tid = threadIdx.x;
    const int rg = tid >> 4, cg = tid & 15;
    float v[4][8];

#pragma unroll
    for (int i = 0; i < 4; ++i) {
        int r = rg * 4 + i;
#pragma unroll
        for (int j = 0; j < 8; ++j) {
            int c = cg * 8 + j;
            v[i][j] = (c < 64) ? g_WLU[(size_t)(pc + r) * 1024 + pc + c]
                               : ((c - 64) == r ? 1.f : 0.f);
        }
    }

    for (int jj = 0; jj < 64; ++jj) {
        if (rg == (jj >> 2)) {
            const int sub = jj & 3;
#pragma unroll
            for (int q = 0; q < 8; ++q) rowbuf[cg * 8 + q] = v[sub][q];
        }
        if (cg == (jj >> 3)) {
            const int subc = jj & 7;
#pragma unroll
            for (int i = 0; i < 4; ++i) colbuf[rg * 4 + i] = v[i][subc];
        }
        __syncthreads();
        const float pinv = 1.0f / rowbuf[jj];
        float f[4];
#pragma unroll
        for (int i = 0; i < 4; ++i) f[i] = colbuf[rg * 4 + i] * pinv;
        float rv[8];
#pragma unroll
        for (int q = 0; q < 8; ++q) rv[q] = rowbuf[cg * 8 + q];
#pragma unroll
        for (int i = 0; i < 4; ++i) {
            if (rg * 4 + i == jj) {
#pragma unroll
                for (int q = 0; q < 8; ++q) v[i][q] = rv[q] * pinv;
            } else {
#pragma unroll
                for (int q = 0; q < 8; ++q) v[i][q] -= f[i] * rv[q];
            }
        }
        __syncthreads();
    }

    // store right half (the inverse)
#pragma unroll
    for (int i = 0; i < 4; ++i) {
        int r = rg * 4 + i;
#pragma unroll
        for (int j = 0; j < 8; ++j) {
            int c = cg * 8 + j;
            if (c >= 64) g_Dinv[r * 64 + (c - 64)] = v[i][j];
        }
    }
}

// ---------------- RP = Dinv @ W[pivot rows][tile] ----------------
__global__ void __launch_bounds__(256) gj_rp_kernel(int kb) {
    __shared__ float Dv[64 * 64];
    __shared__ float Wk[64 * 65];
    const int pc = kb * 64;
    const int c0 = pc + 64 + blockIdx.x * 64;
    const int tid = threadIdx.x;  // 256
    for (int idx = tid; idx < 4096; idx += 256) Dv[idx] = g_Dinv[idx];
    for (int idx = tid; idx < 4096; idx += 256) {
        int k = idx >> 6, c = idx & 63;
        Wk[k * 65 + c] = g_WLU[(size_t)(pc + k) * 1024 + c0 + c];
    }
    __syncthreads();
    const int tr = tid >> 4, tc = tid & 15;
    float rp[4][4] = {};
    for (int k = 0; k < 64; ++k) {
        float w0 = Wk[k * 65 + tc * 4 + 0];
        float w1 = Wk[k * 65 + tc * 4 + 1];
        float w2 = Wk[k * 65 + tc * 4 + 2];
        float w3 = Wk[k * 65 + tc * 4 + 3];
#pragma unroll
        for (int i = 0; i < 4; ++i) {
            float d = Dv[(tr * 4 + i) * 64 + k];
            rp[i][0] += d * w0; rp[i][1] += d * w1; rp[i][2] += d * w2; rp[i][3] += d * w3;
        }
    }
#pragma unroll
    for (int i = 0; i < 4; ++i)
#pragma unroll
        for (int j = 0; j < 4; ++j)
            g_RP[(size_t)(tr * 4 + i) * 1024 + c0 + tc * 4 + j] = rp[i][j];
}

// ---------------- trailing update (+commit in y==7) ----------------
__global__ void __launch_bounds__(256) gj_upd_kernel(int kb) {
    __shared__ float Fs[64 * 65];
    __shared__ float Rs[64 * 65];
    const int pc = kb * 64;
    const int c0 = pc + 64 + blockIdx.x * 64;
    const int tid = threadIdx.x;  // 256
    const int y = blockIdx.y;
    if (y == 7) {  // commit pivot rows for this column tile
        for (int idx = tid; idx < 1024; idx += 256) {
            int r = idx >> 4, c4 = (idx & 15) * 4;
            float4 vv = *(const float4*)&g_RP[(size_t)r * 1024 + c0 + c4];
            *(float4*)&g_WLU[(size_t)(pc + r) * 1024 + c0 + c4] = vv;
        }
        return;
    }
    const int r0 = y * 64 + ((y * 64 >= pc) ? 64 : 0);
    for (int idx = tid; idx < 4096; idx += 256) {
        int r = idx >> 6, k = idx & 63;
        Fs[r * 65 + k] = g_WLU[(size_t)(r0 + r) * 1024 + pc + k];
    }
    for (int idx = tid; idx < 4096; idx += 256) {
        int k = idx >> 6, c = idx & 63;
        Rs[k * 65 + c] = g_RP[(size_t)k * 1024 + c0 + c];
    }
    __syncthreads();
    const int tr = tid >> 4, tc = tid & 15;
    float acc[4][4] = {};
    for (int k = 0; k < 64; ++k) {
        float w0 = Rs[k * 65 + tc * 4 + 0];
        float w1 = Rs[k * 65 + tc * 4 + 1];
        float w2 = Rs[k * 65 + tc * 4 + 2];
        float w3 = Rs[k * 65 + tc * 4 + 3];
#pragma unroll
        for (int i = 0; i < 4; ++i) {
            float f = Fs[(tr * 4 + i) * 65 + k];
            acc[i][0] += f * w0; acc[i][1] += f * w1;
            acc[i][2] += f * w2; acc[i][3] += f * w3;
        }
    }
#pragma unroll
    for (int i = 0; i < 4; ++i) {
        float4* p = (float4*)&g_WLU[(size_t)(r0 + tr * 4 + i) * 1024 + c0 + tc * 4];
        float4 o = *p;
        o.x -= acc[i][0]; o.y -= acc[i][1]; o.z -= acc[i][2]; o.w -= acc[i][3];
        *p = o;
    }
}

// ---------------- recurrence: 1 warp = 1 batch row, blocked fwd-subst ----------------
__global__ void __launch_bounds__(256) rec2_kernel(const float* __restrict__ lam) {
    const int lane = threadIdx.x & 31;
    const int rb = blockIdx.x * 8 + (threadIdx.x >> 5);
    const float* arow = g_a + (size_t)rb * 256;
    float acc[8], linv[8], wv[8];
#pragma unroll
    for (int b = 0; b < 8; ++b) {
        acc[b] = arow[b * 32 + lane];
        linv[b] = 1.0f / lam[b * 32 + lane];
    }
#pragma unroll
    for (int b = 0; b < 8; ++b) {
#pragma unroll 8
        for (int t = 0; t < 32; ++t) {
            int s = b * 32 + t;
            float scaled = acc[b] * linv[b];
            float v = __shfl_sync(0xffffffffu, scaled, t);
            float wt = tanhf(v);
            if (lane == t) wv[b] = wt;
            const float* col = g_D11T + (size_t)s * 256;
            if (lane > t) acc[b] += col[b * 32 + lane] * wt;
#pragma unroll
            for (int b2 = b + 1; b2 < 8; ++b2)
                acc[b2] += col[b2 * 32 + lane] * wt;
        }
    }
#pragma unroll
    for (int b = 0; b < 8; ++b)
        g_wm[(size_t)rb * 256 + b * 32 + lane] = wv[b];
}

// ---------------- 3xTF32 tensor-core NT GEMM ----------------
__device__ __forceinline__ uint32_t f2tf(float f) {
    uint32_t u;
    asm("cvt.rna.tf32.f32 %0, %1;" : "=r"(u) : "f"(f));
    return u;
}
__device__ __forceinline__ void mma8(float& c0, float& c1, float& c2, float& c3,
                                     uint32_t a0, uint32_t a1, uint32_t a2, uint32_t a3,
                                     uint32_t b0, uint32_t b1) {
    asm volatile(
        "mma.sync.aligned.m16n8k8.row.col.f32.tf32.tf32.f32 "
        "{%0,%1,%2,%3},{%4,%5,%6,%7},{%8,%9},{%0,%1,%2,%3};"
        : "+f"(c0), "+f"(c1), "+f"(c2), "+f"(c3)
        : "r"(a0), "r"(a1), "r"(a2), "r"(a3), "r"(b0), "r"(b1));
}

#define ASTRIDE 20
#define ABUF (128 * ASTRIDE)
#define BBUF (64 * ASTRIDE)
#define GEMM_SMEM ((2 * ABUF + 2 * BBUF) * 8)  // 61440

__device__ __forceinline__ void stage_store(uint32_t* Ah, uint32_t* Al,
                                            uint32_t* Bh, uint32_t* Bl,
                                            int arow, int akq, int brow, int bkq,
                                            float4 ra0, float4 ra1, float4 rb0) {
    uint32_t* ah = Ah + arow * ASTRIDE + akq;
    uint32_t* al = Al + arow * ASTRIDE + akq;
    float av[8] = {ra0.x, ra0.y, ra0.z, ra0.w, ra1.x, ra1.y, ra1.z, ra1.w};
#pragma unroll
    for (int j = 0; j < 8; ++j) {
        uint32_t h = f2tf(av[j]);
        ah[j] = h;
        al[j] = f2tf(av[j] - __uint_as_float(h));
    }
    uint32_t* bh = Bh + brow * ASTRIDE + bkq;
    uint32_t* bl = Bl + brow * ASTRIDE + bkq;
    float bv[4] = {rb0.x, rb0.y, rb0.z, rb0.w};
#pragma unroll
    for (int j = 0; j < 4; ++j) {
        uint32_t h = f2tf(bv[j]);
        bh[j] = h;
        bl[j] = f2tf(bv[j] - __uint_as_float(h));
    }
}

__device__ __forceinline__ void gemm_part(const float* __restrict__ A,
                                          const float* __restrict__ Bm,
                                          int K, int ldb, int m0, int n0, int tid,
                                          uint32_t* Ah, uint32_t* Al,
                                          uint32_t* Bh, uint32_t* Bl,
                                          float (&acc)[2][4][4]) {
    const int arow = tid >> 1, akq = (tid & 1) * 8;
    const int brow = tid >> 2, bkq = (tid & 3) * 4;
    const int lane = tid & 31, warp = tid >> 5;
    const int wm = warp >> 1, wn = warp & 1, g = lane >> 2, tg = lane & 3;
    const int nt = K >> 4;
    float4 ra0, ra1, rb0;
    {
        const float* ap = A + (size_t)(m0 + arow) * K + akq;
        ra0 = *(const float4*)ap;
        ra1 = *(const float4*)(ap + 4);
        const float* bp = Bm + (size_t)(n0 + brow) * ldb + bkq;
        rb0 = *(const float4*)bp;
    }
    __syncthreads();
    stage_store(Ah, Al, Bh, Bl, arow, akq, brow, bkq, ra0, ra1, rb0);
    __syncthreads();
    for (int t = 0; t < nt; ++t) {
        const int c = t & 1;
        if (t + 1 < nt) {
            const float* ap = A + (size_t)(m0 + arow) * K + (t + 1) * 16 + akq;
            ra0 = *(const float4*)ap;
            ra1 = *(const float4*)(ap + 4);
            const float* bp = Bm + (size_t)(n0 + brow) * ldb + (t + 1) * 16 + bkq;
            rb0 = *(const float4*)bp;
        }
        const uint32_t* Abh = Ah + c * ABUF;
        const uint32_t* Abl = Al + c * ABUF;
        const uint32_t* Bbh = Bh + c * BBUF;
        const uint32_t* Bbl = Bl + c * BBUF;
#pragma unroll
        for (int ks = 0; ks < 16; ks += 8) {
            uint32_t ah[2][4], al[2][4], bh[4][2], bl[4][2];
#pragma unroll
            for (int i = 0; i < 2; ++i) {
                int r = (wm * 32 + i * 16 + g) * ASTRIDE + ks + tg;
                ah[i][0] = Abh[r];                   al[i][0] = Abl[r];
                ah[i][1] = Abh[r + 8 * ASTRIDE];     al[i][1] = Abl[r + 8 * ASTRIDE];
                ah[i][2] = Abh[r + 4];               al[i][2] = Abl[r + 4];
                ah[i][3] = Abh[r + 8 * ASTRIDE + 4]; al[i][3] = Abl[r + 8 * ASTRIDE + 4];
            }
#pragma unroll
            for (int j = 0; j < 4; ++j) {
                int r = (wn * 32 + j * 8 + g) * ASTRIDE + ks + tg;
                bh[j][0] = Bbh[r];     bl[j][0] = Bbl[r];
                bh[j][1] = Bbh[r + 4]; bl[j][1] = Bbl[r + 4];
            }
#pragma unroll
            for (int i = 0; i < 2; ++i)
#pragma unroll
                for (int j = 0; j < 4; ++j) {
                    mma8(acc[i][j][0], acc[i][j][1], acc[i][j][2], acc[i][j][3],
                         al[i][0], al[i][1], al[i][2], al[i][3], bh[j][0], bh[j][1]);
                    mma8(acc[i][j][0], acc[i][j][1], acc[i][j][2], acc[i][j][3],
                         ah[i][0], ah[i][1], ah[i][2], ah[i][3], bl[j][0], bl[j][1]);
                    mma8(acc[i][j][0], acc[i][j][1], acc[i][j][2], acc[i][j][3],
                         ah[i][0], ah[i][1], ah[i][2], ah[i][3], bh[j][0], bh[j][1]);
                }
        }
        __syncthreads();
        if (t + 1 < nt) {
            stage_store(Ah + (1 - c) * ABUF, Al + (1 - c) * ABUF,
                        Bh + (1 - c) * BBUF, Bl + (1 - c) * BBUF,
                        arow, akq, brow, bkq, ra0, ra1, rb0);
            __syncthreads();
        }
    }
}

__global__ void __launch_bounds__(256) gemm3_kernel(
    float* __restrict__ C, int N, const float* __restrict__ bias,
    const float* A0, const float* B0, int K0, int l0,
    const float* A1, const float* B1, int K1, int l1) {
    extern __shared__ uint32_t sm_u[];
    uint32_t* Ah = sm_u;
    uint32_t* Bh = Ah + 2 * ABUF;
    uint32_t* Al = Bh + 2 * BBUF;
    uint32_t* Bl = Al + 2 * ABUF;
    const int tid = threadIdx.x;
    const int m0 = blockIdx.y * 128, n0 = blockIdx.x * 64;
    float acc[2][4][4];
#pragma unroll
    for (int i = 0; i < 2; ++i)
#pragma unroll
        for (int j = 0; j < 4; ++j)
#pragma unroll
            for (int q = 0; q < 4; ++q) acc[i][j][q] = 0.f;

    gemm_part(A0, B0, K0, l0, m0, n0, tid, Ah, Al, Bh, Bl, acc);
    if (A1) gemm_part(A1, B1, K1, l1, m0, n0, tid, Ah, Al, Bh, Bl, acc);

    const int lane = tid & 31, warp = tid >> 5;
    const int wm = warp >> 1, wn = warp & 1, g = lane >> 2, tg = lane & 3;
#pragma unroll
    for (int i = 0; i < 2; ++i)
#pragma unroll
        for (int j = 0; j < 4; ++j) {
            int r = m0 + wm * 32 + i * 16 + g;
            int cc = n0 + wn * 32 + j * 8 + 2 * tg;
            float2 bb = make_float2(0.f, 0.f);
            if (bias) bb = *(const float2*)&bias[cc];
            *(float2*)&C[(size_t)r * N + cc] =
                make_float2(acc[i][j][0] + bb.x, acc[i][j][1] + bb.y);
            *(float2*)&C[(size_t)(r + 8) * N + cc] =
                make_float2(acc[i][j][2] + bb.x, acc[i][j][3] + bb.y);
        }
}

// ---------------- launch ----------------
extern "C" void kernel_launch(void* const* d_in, const int* in_sizes, int n_in,
                              void* d_out, int out_size) {
    const float *u, *x0, *C1, *D11, *D12, *lam, *Fm, *B1, *B2, *E, *C2, *D21, *D22;
    if (in_sizes[0] == BATCH * DIN) {
        u   = (const float*)d_in[0];  x0  = (const float*)d_in[1];
        C1  = (const float*)d_in[2];  D11 = (const float*)d_in[3];
        D12 = (const float*)d_in[4];  lam = (const float*)d_in[5];
        Fm  = (const float*)d_in[6];  B1  = (const float*)d_in[7];
        B2  = (const float*)d_in[8];  E   = (const float*)d_in[9];
        C2  = (const float*)d_in[10]; D21 = (const float*)d_in[11];
        D22 = (const float*)d_in[12];
    } else {
        C1  = (const float*)d_in[0];  D11 = (const float*)d_in[1];
        D12 = (const float*)d_in[2];  lam = (const float*)d_in[3];
        Fm  = (const float*)d_in[4];  B1  = (const float*)d_in[5];
        B2  = (const float*)d_in[6];  E   = (const float*)d_in[7];
        C2  = (const float*)d_in[8];  D21 = (const float*)d_in[9];
        D22 = (const float*)d_in[10]; u   = (const float*)d_in[11];
        x0  = (const float*)d_in[12];
    }
    (void)D21;  // identically zero by construction

    cudaFuncSetAttribute(gemm3_kernel,
                         cudaFuncAttributeMaxDynamicSharedMemorySize, GEMM_SMEM);

    float *pA, *pW, *pRhs, *pXn, *pWLU, *pC1x0, *pFx0;
    cudaGetSymbolAddress((void**)&pA, g_a);
    cudaGetSymbolAddress((void**)&pW, g_wm);
    cudaGetSymbolAddress((void**)&pRhs, g_rhs);
    cudaGetSymbolAddress((void**)&pXn, g_xn);
    cudaGetSymbolAddress((void**)&pWLU, g_WLU);
    cudaGetSymbolAddress((void**)&pC1x0, g_c1x0);
    cudaGetSymbolAddress((void**)&pFx0, g_fx0);

    // --- E inverse via blocked Gauss-Jordan ---
    gj_init_kernel<<<512, 256>>>(E);
    for (int kb = 0; kb < 8; ++kb) {
        gj_pivot_fast<<<1, 256>>>(kb);
        gj_rp_kernel<<<15 - kb, 256>>>(kb);
        gj_upd_kernel<<<dim3(15 - kb, 8), 256>>>(kb);
    }

    // --- small prep ---
    d11t_kernel<<<dim3(8, 8), dim3(32, 8)>>>(D11);
    mv_kernel<<<4, 64>>>(C1, x0, DNL, DIN, 0);
    mv_kernel<<<8, 64>>>(Fm, x0, DINT, DINT, 1);

    // --- a = u @ D12^T + c1x0 ---
    gemm3_kernel<<<dim3(4, 16), 256, GEMM_SMEM>>>(
        pA, 256, pC1x0,
        u, D12, 512, 512,
        nullptr, nullptr, 0, 0);

    // --- sequential nonlinearity ---
    rec2_kernel<<<256, 256>>>(lam);

    // --- rhs = w @ B1^T + u @ B2^T + fx0 ---
    gemm3_kernel<<<dim3(8, 16), 256, GEMM_SMEM>>>(
        pRhs, 512, pFx0,
        pW, B1, 256, 256,
        u, B2, 512, 512);

    // --- x_new = rhs @ Einv^T ---
    gemm3_kernel<<<dim3(8, 16), 256, GEMM_SMEM>>>(
        pXn, 512, nullptr,
        pRhs, pWLU + 512, 512, 1024,
        nullptr, nullptr, 0, 0);

    // --- y = x_new @ C2^T + u @ D22^T ---
    gemm3_kernel<<<dim3(8, 16), 256, GEMM_SMEM>>>(
        (float*)d_out, 512, nullptr,
        pXn, C2, 512, 512,
        u, D22, 512, 512);
}